// round 2
// baseline (speedup 1.0000x reference)
#include <cuda_runtime.h>

// ---------------------------------------------------------------------------
// WMSA (shifted-window attention), b=4, H=W=256, c=256, WS=8, HEAD_DIM=32
//   n_heads = 8, windows = 32x32 = 1024 per batch, P = 64 tokens/window
// Phases:
//   1) qkv_gemm : fused roll+window-gather + QKV projection (M=262144,N=768,K=256)
//   2) attn     : per (b,win,head) 64x64 attention w/ rel-pos bias + shift mask
//   3) out_gemm : output projection + bias; epilogue reproduces the reference's
//                 scrambled (nW,b)->batch/window reshape, then roll(+4,+4).
//
// Reference quirk: out.transpose(1,0,2,3,4).reshape(b,hw,ww,WS,WS,c) flattens
// (nW, b, ...) and re-slices it as (b, 32, 32, ...). For attention output
// element (b_, n, p, h, d), let L = n*4 + b_. Then
//   batch = L>>10, win_row = (L>>5)&31, win_col = L&31,
//   H = win_row*8 + (p>>3), W = win_col*8 + (p&7), chan = h*32+d,
// followed by roll(+4,+4).
// ---------------------------------------------------------------------------

#define QKV_SCALE 0.1767766952966369f   // 32^-0.5

// Scratch (allocation-free rule: __device__ globals). 268 MB each.
__device__ float g_q[67108864];   // [b,win,head,p,d] = [4,1024,8,64,32]
__device__ float g_k[67108864];
__device__ float g_v[67108864];
__device__ float g_att[67108864]; // [b,win,p,c] = [4,1024,64,256]

// ---------------------------------------------------------------------------
// Kernel 1: QKV GEMM.  out[t,n] = sum_k x[src(t),k] * w_qkv[n,k] + b_qkv[n]
// 128x128 tile, BK=8, 256 threads, 8x8 per thread.
// grid = (6, 2048): bn fastest so the A tile stays L2-resident across bn.
// ---------------------------------------------------------------------------
__global__ __launch_bounds__(256) void qkv_gemm(const float* __restrict__ x,
                                                const float* __restrict__ w,
                                                const float* __restrict__ bias) {
    __shared__ float As[8][128];
    __shared__ float Bs[8][128];
    const int tid = threadIdx.x;
    const int bn = blockIdx.x;       // 0..5   (128-col slab of N=768)
    const int bm = blockIdx.y;       // 0..2047

    const int lrow = tid >> 1;       // 0..127
    const int lcol = (tid & 1) << 2; // 0 or 4

    // A source row: token t -> rolled spatial position in x
    const int t    = bm * 128 + lrow;
    const int bi   = t >> 16;
    const int rem  = t & 65535;
    const int win  = rem >> 6;
    const int p    = rem & 63;
    const int hh   = (((win >> 5) << 3) + (p >> 3) + 4) & 255;
    const int wwp  = (((win & 31) << 3) + (p & 7) + 4) & 255;
    const float* a_ptr = x + ((((size_t)bi << 8) + hh) * 256 + wwp) * 256 + lcol;
    const float* b_ptr = w + (size_t)(bn * 128 + lrow) * 256 + lcol;

    float acc[8][8];
#pragma unroll
    for (int i = 0; i < 8; i++)
#pragma unroll
        for (int j = 0; j < 8; j++) acc[i][j] = 0.f;

    const int ty = tid >> 4, tx = tid & 15;

    for (int kt = 0; kt < 256; kt += 8) {
        float4 av = *(const float4*)(a_ptr + kt);
        float4 bv = *(const float4*)(b_ptr + kt);
        As[lcol + 0][lrow] = av.x;
        As[lcol + 1][lrow] = av.y;
        As[lcol + 2][lrow] = av.z;
        As[lcol + 3][lrow] = av.w;
        Bs[lcol + 0][lrow] = bv.x;
        Bs[lcol + 1][lrow] = bv.y;
        Bs[lcol + 2][lrow] = bv.z;
        Bs[lcol + 3][lrow] = bv.w;
        __syncthreads();
#pragma unroll
        for (int kk = 0; kk < 8; kk++) {
            float ar[8], br[8];
            *(float4*)(ar)     = *(const float4*)&As[kk][ty * 8];
            *(float4*)(ar + 4) = *(const float4*)&As[kk][ty * 8 + 4];
            *(float4*)(br)     = *(const float4*)&Bs[kk][tx * 8];
            *(float4*)(br + 4) = *(const float4*)&Bs[kk][tx * 8 + 4];
#pragma unroll
            for (int i = 0; i < 8; i++)
#pragma unroll
                for (int j = 0; j < 8; j++) acc[i][j] += ar[i] * br[j];
        }
        __syncthreads();
    }

    // Epilogue: scatter into per-head q/k/v scratch. Each 128-col slab is
    // entirely q (bn<2), k (bn<4) or v.
    float* dst = g_q;
    if (bn >= 2) dst = g_k;
    if (bn >= 4) dst = g_v;
    const bool isq = (bn < 2);

#pragma unroll
    for (int i = 0; i < 8; i++) {
        const int gt   = bm * 128 + ty * 8 + i;
        const int gbi  = gt >> 16;
        const int grem = gt & 65535;
        const int gwin = grem >> 6;
        const int gp   = grem & 63;
        const size_t rowbase = (size_t)(gbi * 1024 + gwin) * 16384 + gp * 32;
#pragma unroll
        for (int j = 0; j < 8; j++) {
            const int n    = bn * 128 + tx * 8 + j;
            const int head = (n >> 5) & 7;
            const int d    = n & 31;
            float v = acc[i][j] + bias[n];
            if (isq) v *= QKV_SCALE;
            dst[rowbase + head * 2048 + d] = v;
        }
    }
}

// ---------------------------------------------------------------------------
// Kernel 2: attention per (b, win, head).  64 threads = one row each.
// ---------------------------------------------------------------------------
__global__ __launch_bounds__(64) void attn_kernel(const float* __restrict__ rel_pos) {
    const int blk  = blockIdx.x;       // ((b*1024+win)*8+head)
    const int head = blk & 7;
    const int bw   = blk >> 3;         // b*1024+win
    const int win  = bw & 1023;
    const bool lastH = ((win >> 5) == 31);
    const bool lastW = ((win & 31) == 31);
    const int p = threadIdx.x;

    __shared__ float k_s[32][65];      // [d][j], padded: conflict-free stores
    __shared__ float v_s[32][65];
    __shared__ float rel_s[240];

    const size_t base = (size_t)blk * 2048;

#pragma unroll
    for (int d4 = 0; d4 < 32; d4 += 4) {
        float4 kv = *(const float4*)&g_k[base + p * 32 + d4];
        k_s[d4 + 0][p] = kv.x; k_s[d4 + 1][p] = kv.y;
        k_s[d4 + 2][p] = kv.z; k_s[d4 + 3][p] = kv.w;
        float4 vv = *(const float4*)&g_v[base + p * 32 + d4];
        v_s[d4 + 0][p] = vv.x; v_s[d4 + 1][p] = vv.y;
        v_s[d4 + 2][p] = vv.z; v_s[d4 + 3][p] = vv.w;
    }
    {
        const float* rp = rel_pos + head * 225;
        for (int i = p; i < 225; i += 64) rel_s[i] = rp[i];
    }

    float qreg[32];
#pragma unroll
    for (int d4 = 0; d4 < 32; d4 += 4) {
        float4 qv = *(const float4*)&g_q[base + p * 32 + d4];
        qreg[d4] = qv.x; qreg[d4 + 1] = qv.y;
        qreg[d4 + 2] = qv.z; qreg[d4 + 3] = qv.w;
    }
    __syncthreads();

    const int pi = p >> 3, pj = p & 7;
    const bool ph4 = (pi < 4), pw4 = (pj < 4);

    float sc[64];
    float mx = -3.0e38f;
#pragma unroll
    for (int j = 0; j < 64; j++) {
        float s = 0.f;
#pragma unroll
        for (int d = 0; d < 32; d++) s += qreg[d] * k_s[d][j];
        const int qi = j >> 3, qj = j & 7;
        s += rel_s[(pi - qi + 7) * 15 + (pj - qj + 7)];
        if ((lastH && (ph4 != (qi < 4))) || (lastW && (pw4 != (qj < 4))))
            s = -1e30f;
        sc[j] = s;
        mx = fmaxf(mx, s);
    }

    float sum = 0.f;
#pragma unroll
    for (int j = 0; j < 64; j++) {
        float e = __expf(sc[j] - mx);
        sc[j] = e;
        sum += e;
    }
    const float inv = 1.f / sum;

    float o[32];
#pragma unroll
    for (int d = 0; d < 32; d++) o[d] = 0.f;
#pragma unroll
    for (int j = 0; j < 64; j++) {
        const float a = sc[j] * inv;
#pragma unroll
        for (int d = 0; d < 32; d++) o[d] += a * v_s[d][j];
    }

    float* op = g_att + (size_t)bw * 16384 + p * 256 + head * 32;
#pragma unroll
    for (int d4 = 0; d4 < 32; d4 += 4)
        *(float4*)(op + d4) = make_float4(o[d4], o[d4 + 1], o[d4 + 2], o[d4 + 3]);
}

// ---------------------------------------------------------------------------
// Kernel 3: output projection + bias; scatter per the reference's scrambled
// (nW,b) reshape, then roll(+4,+4).
// ---------------------------------------------------------------------------
__global__ __launch_bounds__(256) void out_gemm(const float* __restrict__ w,
                                                const float* __restrict__ bias,
                                                float* __restrict__ out) {
    __shared__ float As[8][128];
    __shared__ float Bs[8][128];
    const int tid = threadIdx.x;
    const int bn = blockIdx.x;       // 0..1
    const int bm = blockIdx.y;       // 0..2047

    const int lrow = tid >> 1;
    const int lcol = (tid & 1) << 2;
    const float* a_ptr = g_att + (size_t)(bm * 128 + lrow) * 256 + lcol;
    const float* b_ptr = w + (size_t)(bn * 128 + lrow) * 256 + lcol;

    float acc[8][8];
#pragma unroll
    for (int i = 0; i < 8; i++)
#pragma unroll
        for (int j = 0; j < 8; j++) acc[i][j] = 0.f;

    const int ty = tid >> 4, tx = tid & 15;

    for (int kt = 0; kt < 256; kt += 8) {
        float4 av = *(const float4*)(a_ptr + kt);
        float4 bv = *(const float4*)(b_ptr + kt);
        As[lcol + 0][lrow] = av.x;
        As[lcol + 1][lrow] = av.y;
        As[lcol + 2][lrow] = av.z;
        As[lcol + 3][lrow] = av.w;
        Bs[lcol + 0][lrow] = bv.x;
        Bs[lcol + 1][lrow] = bv.y;
        Bs[lcol + 2][lrow] = bv.z;
        Bs[lcol + 3][lrow] = bv.w;
        __syncthreads();
#pragma unroll
        for (int kk = 0; kk < 8; kk++) {
            float ar[8], br[8];
            *(float4*)(ar)     = *(const float4*)&As[kk][ty * 8];
            *(float4*)(ar + 4) = *(const float4*)&As[kk][ty * 8 + 4];
            *(float4*)(br)     = *(const float4*)&Bs[kk][tx * 8];
            *(float4*)(br + 4) = *(const float4*)&Bs[kk][tx * 8 + 4];
#pragma unroll
            for (int i = 0; i < 8; i++)
#pragma unroll
                for (int j = 0; j < 8; j++) acc[i][j] += ar[i] * br[j];
        }
        __syncthreads();
    }

#pragma unroll
    for (int i = 0; i < 8; i++) {
        const int gt   = bm * 128 + ty * 8 + i;
        const int gbi  = gt >> 16;        // b_ (attention batch)
        const int grem = gt & 65535;
        const int gwin = grem >> 6;       // n  (true window id)
        const int gp   = grem & 63;       // p  (window-local token)
        // Reference's scrambled reshape: L = n*4 + b_
        const int L  = gwin * 4 + gbi;
        const int a  = L >> 10;           // output batch
        const int r  = (L >> 5) & 31;     // output window row
        const int s  = L & 31;            // output window col
        const int hh  = ((r << 3) + (gp >> 3) + 4) & 255;
        const int wwp = ((s << 3) + (gp & 7) + 4) & 255;
        float* orow = out + ((((size_t)a << 8) + hh) * 256 + wwp) * 256;
#pragma unroll
        for (int j = 0; j < 8; j++) {
            const int n = bn * 128 + tx * 8 + j;
            orow[n] = acc[i][j] + bias[n];
        }
    }
}

// ---------------------------------------------------------------------------
extern "C" void kernel_launch(void* const* d_in, const int* in_sizes, int n_in,
                              void* d_out, int out_size) {
    const float* x      = (const float*)d_in[0];
    const float* w_qkv  = (const float*)d_in[1];
    const float* b_qkv  = (const float*)d_in[2];
    const float* rel    = (const float*)d_in[3];
    const float* w_out  = (const float*)d_in[4];
    const float* b_out  = (const float*)d_in[5];
    float* out = (float*)d_out;

    qkv_gemm<<<dim3(6, 2048), 256>>>(x, w_qkv, b_qkv);
    attn_kernel<<<32768, 64>>>(rel);
    out_gemm<<<dim3(2, 2048), 256>>>(w_out, b_out, out);
}

// round 4
// speedup vs baseline: 1.1815x; 1.1815x over previous
#include <cuda_runtime.h>
#include <cuda_bf16.h>
#include <cstdint>

// ---------------------------------------------------------------------------
// WMSA, b=4, H=W=256, c=256, WS=8, HEAD_DIM=32.
// R4: tcgen05 is unavailable (harness PTX target is compute_103, no 'a'),
// so both projections use warp-level mma.sync m16n8k16 bf16 (HMMA tensor path)
// with a 3-term hi/lo split for fp32-class accuracy.
// ---------------------------------------------------------------------------

#define QKV_SCALE 0.1767766952966369f   // 32^-0.5

__device__ float g_q[67108864];   // [b,win,head,p,d]
__device__ float g_k[67108864];
__device__ float g_v[67108864];
__device__ float g_att[67108864]; // [b,win,p,c]

// ---------------- helpers ----------------
__device__ __forceinline__ uint32_t smem_u32(const void* p) {
    uint32_t a;
    asm("{ .reg .u64 t; cvta.to.shared.u64 t, %1; cvt.u32.u64 %0, t; }"
        : "=r"(a) : "l"(p));
    return a;
}
__device__ __forceinline__ void ldmx4(uint32_t* r, uint32_t addr) {
    asm volatile("ldmatrix.sync.aligned.m8n8.x4.shared.b16 {%0,%1,%2,%3}, [%4];"
                 : "=r"(r[0]), "=r"(r[1]), "=r"(r[2]), "=r"(r[3]) : "r"(addr));
}
__device__ __forceinline__ void mma_bf16(float* c, const uint32_t* a,
                                         uint32_t b0, uint32_t b1) {
    asm volatile(
        "mma.sync.aligned.m16n8k16.row.col.f32.bf16.bf16.f32 "
        "{%0,%1,%2,%3}, {%4,%5,%6,%7}, {%8,%9}, {%0,%1,%2,%3};"
        : "+f"(c[0]), "+f"(c[1]), "+f"(c[2]), "+f"(c[3])
        : "r"(a[0]), "r"(a[1]), "r"(a[2]), "r"(a[3]), "r"(b0), "r"(b1));
}

// Convert 16 consecutive fp32 -> bf16 hi and lo (lo = rn(v - hi)), store packed.
__device__ __forceinline__ void cvt_store16(__nv_bfloat16* hi, __nv_bfloat16* lo,
                                            const float* src) {
#pragma unroll
    for (int i = 0; i < 4; i++) {
        float4 v = *(const float4*)(src + i * 4);
        __nv_bfloat16 hx = __float2bfloat16(v.x);
        __nv_bfloat16 hy = __float2bfloat16(v.y);
        __nv_bfloat16 hz = __float2bfloat16(v.z);
        __nv_bfloat16 hw = __float2bfloat16(v.w);
        uint2 ph;
        ph.x = (uint32_t)__bfloat16_as_ushort(hx) | ((uint32_t)__bfloat16_as_ushort(hy) << 16);
        ph.y = (uint32_t)__bfloat16_as_ushort(hz) | ((uint32_t)__bfloat16_as_ushort(hw) << 16);
        *(uint2*)(hi + i * 4) = ph;
        __nv_bfloat16 lx = __float2bfloat16(v.x - __bfloat162float(hx));
        __nv_bfloat16 ly = __float2bfloat16(v.y - __bfloat162float(hy));
        __nv_bfloat16 lz = __float2bfloat16(v.z - __bfloat162float(hz));
        __nv_bfloat16 lw = __float2bfloat16(v.w - __bfloat162float(hw));
        uint2 pl;
        pl.x = (uint32_t)__bfloat16_as_ushort(lx) | ((uint32_t)__bfloat16_as_ushort(ly) << 16);
        pl.y = (uint32_t)__bfloat16_as_ushort(lz) | ((uint32_t)__bfloat16_as_ushort(lw) << 16);
        *(uint2*)(lo + i * 4) = pl;
    }
}

// Shared tile: 128 rows x 32 k-chunk, stride 40 bf16 (80B) -> ldmatrix
// 8-row groups hit all 32 banks exactly once.
#define TSTR 40

// ---------------------------------------------------------------------------
// Kernel 1: QKV projection. 128x128 tile, K=256 in 8 chunks of 32,
// 3 split pairs per chunk (hi*hi, lo*hi, hi*lo).
// ---------------------------------------------------------------------------
__global__ __launch_bounds__(256, 2)
void qkv_gemm_tc(const float* __restrict__ x,
                 const float* __restrict__ w,
                 const float* __restrict__ bias) {
    __shared__ __nv_bfloat16 sAhi[128 * TSTR];
    __shared__ __nv_bfloat16 sAlo[128 * TSTR];
    __shared__ __nv_bfloat16 sBhi[128 * TSTR];
    __shared__ __nv_bfloat16 sBlo[128 * TSTR];

    const int tid = threadIdx.x;
    const int bn = blockIdx.x;   // 0..5
    const int bm = blockIdx.y;   // 0..2047
    const int lane = tid & 31;
    const int wid  = tid >> 5;
    const int warpM = wid & 1;   // 2 x 64 rows
    const int warpN = wid >> 1;  // 4 x 32 cols

    // Staging source rows
    const int row  = tid >> 1;
    const int half = tid & 1;
    const int t    = bm * 128 + row;
    const int bi   = t >> 16;
    const int rem  = t & 65535;
    const int win  = rem >> 6;
    const int p    = rem & 63;
    const int hh   = (((win >> 5) << 3) + (p >> 3) + 4) & 255;
    const int wwp  = (((win & 31) << 3) + (p & 7) + 4) & 255;
    const float* a_row = x + ((((size_t)bi << 8) + hh) * 256 + wwp) * 256;
    const float* b_row = w + (size_t)(bn * 128 + row) * 256;

    const uint32_t uAhi = smem_u32(sAhi), uAlo = smem_u32(sAlo);
    const uint32_t uBhi = smem_u32(sBhi), uBlo = smem_u32(sBlo);
    // ldmatrix lane offset: rows (lane&15), 8-col block (lane>>4)
    const uint32_t lane_off = (uint32_t)((lane & 15) * (TSTR * 2) + (lane >> 4) * 16);

    float acc[4][4][4];
#pragma unroll
    for (int a = 0; a < 4; a++)
#pragma unroll
        for (int b = 0; b < 4; b++)
#pragma unroll
            for (int cR = 0; cR < 4; cR++) acc[a][b][cR] = 0.f;

    for (int c = 0; c < 8; c++) {
        cvt_store16(sAhi + row * TSTR + half * 16, sAlo + row * TSTR + half * 16,
                    a_row + c * 32 + half * 16);
        cvt_store16(sBhi + row * TSTR + half * 16, sBlo + row * TSTR + half * 16,
                    b_row + c * 32 + half * 16);
        __syncthreads();

#pragma unroll
        for (int pr = 0; pr < 3; pr++) {
            const uint32_t aB = (pr == 1) ? uAlo : uAhi;
            const uint32_t bB = (pr == 2) ? uBlo : uBhi;
#pragma unroll
            for (int ks = 0; ks < 2; ks++) {
                uint32_t af[4][4];
#pragma unroll
                for (int mf = 0; mf < 4; mf++)
                    ldmx4(af[mf], aB + (warpM * 64 + mf * 16) * (TSTR * 2)
                                     + ks * 32 + lane_off);
                uint32_t bf[2][4];
#pragma unroll
                for (int np = 0; np < 2; np++)
                    ldmx4(bf[np], bB + (warpN * 32 + np * 16) * (TSTR * 2)
                                     + ks * 32 + lane_off);
#pragma unroll
                for (int mf = 0; mf < 4; mf++)
#pragma unroll
                    for (int nf = 0; nf < 4; nf++)
                        mma_bf16(acc[mf][nf], af[mf],
                                 bf[nf >> 1][nf & 1], bf[nf >> 1][(nf & 1) + 2]);
            }
        }
        __syncthreads();
    }

    // Epilogue: scatter to q/k/v scratch with bias (+scale for q).
    float* dst = (bn < 2) ? g_q : ((bn < 4) ? g_k : g_v);
    const bool isq = (bn < 2);
#pragma unroll
    for (int mf = 0; mf < 4; mf++) {
#pragma unroll
        for (int rr = 0; rr < 2; rr++) {
            const int gt   = bm * 128 + warpM * 64 + mf * 16 + (lane >> 2) + rr * 8;
            const int gbi  = gt >> 16;
            const int grem = gt & 65535;
            const int gwin = grem >> 6;
            const int gp   = grem & 63;
            const size_t rowbase = (size_t)(gbi * 1024 + gwin) * 16384 + gp * 32;
#pragma unroll
            for (int nf = 0; nf < 4; nf++) {
                const int n = bn * 128 + warpN * 32 + nf * 8 + (lane & 3) * 2;
                float v0 = acc[mf][nf][rr * 2 + 0] + __ldg(bias + n);
                float v1 = acc[mf][nf][rr * 2 + 1] + __ldg(bias + n + 1);
                if (isq) { v0 *= QKV_SCALE; v1 *= QKV_SCALE; }
                float2 pv = make_float2(v0, v1);
                *(float2*)&dst[rowbase + ((n >> 5) & 7) * 2048 + (n & 31)] = pv;
            }
        }
    }
}

// ---------------------------------------------------------------------------
// Kernel 2: attention per (b, win, head). 64 threads = one row each. (unchanged)
// ---------------------------------------------------------------------------
__global__ __launch_bounds__(64) void attn_kernel(const float* __restrict__ rel_pos) {
    const int blk  = blockIdx.x;
    const int head = blk & 7;
    const int bw   = blk >> 3;
    const int win  = bw & 1023;
    const bool lastH = ((win >> 5) == 31);
    const bool lastW = ((win & 31) == 31);
    const int p = threadIdx.x;

    __shared__ float k_s[32][65];
    __shared__ float v_s[32][65];
    __shared__ float rel_s[240];

    const size_t base = (size_t)blk * 2048;

#pragma unroll
    for (int d4 = 0; d4 < 32; d4 += 4) {
        float4 kv = *(const float4*)&g_k[base + p * 32 + d4];
        k_s[d4 + 0][p] = kv.x; k_s[d4 + 1][p] = kv.y;
        k_s[d4 + 2][p] = kv.z; k_s[d4 + 3][p] = kv.w;
        float4 vv = *(const float4*)&g_v[base + p * 32 + d4];
        v_s[d4 + 0][p] = vv.x; v_s[d4 + 1][p] = vv.y;
        v_s[d4 + 2][p] = vv.z; v_s[d4 + 3][p] = vv.w;
    }
    {
        const float* rp = rel_pos + head * 225;
        for (int i = p; i < 225; i += 64) rel_s[i] = rp[i];
    }

    float qreg[32];
#pragma unroll
    for (int d4 = 0; d4 < 32; d4 += 4) {
        float4 qv = *(const float4*)&g_q[base + p * 32 + d4];
        qreg[d4] = qv.x; qreg[d4 + 1] = qv.y;
        qreg[d4 + 2] = qv.z; qreg[d4 + 3] = qv.w;
    }
    __syncthreads();

    const int pi = p >> 3, pj = p & 7;
    const bool ph4 = (pi < 4), pw4 = (pj < 4);

    float sc[64];
    float mx = -3.0e38f;
#pragma unroll
    for (int j = 0; j < 64; j++) {
        float s = 0.f;
#pragma unroll
        for (int d = 0; d < 32; d++) s += qreg[d] * k_s[d][j];
        const int qi = j >> 3, qj = j & 7;
        s += rel_s[(pi - qi + 7) * 15 + (pj - qj + 7)];
        if ((lastH && (ph4 != (qi < 4))) || (lastW && (pw4 != (qj < 4))))
            s = -1e30f;
        sc[j] = s;
        mx = fmaxf(mx, s);
    }

    float sum = 0.f;
#pragma unroll
    for (int j = 0; j < 64; j++) {
        float e = __expf(sc[j] - mx);
        sc[j] = e;
        sum += e;
    }
    const float inv = 1.f / sum;

    float o[32];
#pragma unroll
    for (int d = 0; d < 32; d++) o[d] = 0.f;
#pragma unroll
    for (int j = 0; j < 64; j++) {
        const float a = sc[j] * inv;
#pragma unroll
        for (int d = 0; d < 32; d++) o[d] += a * v_s[d][j];
    }

    float* op = g_att + (size_t)bw * 16384 + p * 256 + head * 32;
#pragma unroll
    for (int d4 = 0; d4 < 32; d4 += 4)
        *(float4*)(op + d4) = make_float4(o[d4], o[d4 + 1], o[d4 + 2], o[d4 + 3]);
}

// ---------------------------------------------------------------------------
// Kernel 3: output projection (same mma plumbing); epilogue reproduces the
// reference's scrambled (nW,b) reshape, then roll(+4,+4).
// ---------------------------------------------------------------------------
__global__ __launch_bounds__(256, 2)
void out_gemm_tc(const float* __restrict__ w,
                 const float* __restrict__ bias,
                 float* __restrict__ out) {
    __shared__ __nv_bfloat16 sAhi[128 * TSTR];
    __shared__ __nv_bfloat16 sAlo[128 * TSTR];
    __shared__ __nv_bfloat16 sBhi[128 * TSTR];
    __shared__ __nv_bfloat16 sBlo[128 * TSTR];

    const int tid = threadIdx.x;
    const int bn = blockIdx.x;   // 0..1
    const int bm = blockIdx.y;   // 0..2047
    const int lane = tid & 31;
    const int wid  = tid >> 5;
    const int warpM = wid & 1;
    const int warpN = wid >> 1;

    const int row  = tid >> 1;
    const int half = tid & 1;
    const float* a_row = g_att + (size_t)(bm * 128 + row) * 256;
    const float* b_row = w + (size_t)(bn * 128 + row) * 256;

    const uint32_t uAhi = smem_u32(sAhi), uAlo = smem_u32(sAlo);
    const uint32_t uBhi = smem_u32(sBhi), uBlo = smem_u32(sBlo);
    const uint32_t lane_off = (uint32_t)((lane & 15) * (TSTR * 2) + (lane >> 4) * 16);

    float acc[4][4][4];
#pragma unroll
    for (int a = 0; a < 4; a++)
#pragma unroll
        for (int b = 0; b < 4; b++)
#pragma unroll
            for (int cR = 0; cR < 4; cR++) acc[a][b][cR] = 0.f;

    for (int c = 0; c < 8; c++) {
        cvt_store16(sAhi + row * TSTR + half * 16, sAlo + row * TSTR + half * 16,
                    a_row + c * 32 + half * 16);
        cvt_store16(sBhi + row * TSTR + half * 16, sBlo + row * TSTR + half * 16,
                    b_row + c * 32 + half * 16);
        __syncthreads();

#pragma unroll
        for (int pr = 0; pr < 3; pr++) {
            const uint32_t aB = (pr == 1) ? uAlo : uAhi;
            const uint32_t bB = (pr == 2) ? uBlo : uBhi;
#pragma unroll
            for (int ks = 0; ks < 2; ks++) {
                uint32_t af[4][4];
#pragma unroll
                for (int mf = 0; mf < 4; mf++)
                    ldmx4(af[mf], aB + (warpM * 64 + mf * 16) * (TSTR * 2)
                                     + ks * 32 + lane_off);
                uint32_t bf[2][4];
#pragma unroll
                for (int np = 0; np < 2; np++)
                    ldmx4(bf[np], bB + (warpN * 32 + np * 16) * (TSTR * 2)
                                     + ks * 32 + lane_off);
#pragma unroll
                for (int mf = 0; mf < 4; mf++)
#pragma unroll
                    for (int nf = 0; nf < 4; nf++)
                        mma_bf16(acc[mf][nf], af[mf],
                                 bf[nf >> 1][nf & 1], bf[nf >> 1][(nf & 1) + 2]);
            }
        }
        __syncthreads();
    }

#pragma unroll
    for (int mf = 0; mf < 4; mf++) {
#pragma unroll
        for (int rr = 0; rr < 2; rr++) {
            const int gt   = bm * 128 + warpM * 64 + mf * 16 + (lane >> 2) + rr * 8;
            const int gbi  = gt >> 16;        // b_ (attention batch)
            const int grem = gt & 65535;
            const int gwin = grem >> 6;       // n (true window id)
            const int gp   = grem & 63;
            const int L  = gwin * 4 + gbi;    // reference's scrambled flatten
            const int a  = L >> 10;
            const int r  = (L >> 5) & 31;
            const int s  = L & 31;
            const int hh  = ((r << 3) + (gp >> 3) + 4) & 255;
            const int wwp = ((s << 3) + (gp & 7) + 4) & 255;
            float* orow = out + ((((size_t)a << 8) + hh) * 256 + wwp) * 256;
#pragma unroll
            for (int nf = 0; nf < 4; nf++) {
                const int n = bn * 128 + warpN * 32 + nf * 8 + (lane & 3) * 2;
                float2 pv = make_float2(acc[mf][nf][rr * 2 + 0] + __ldg(bias + n),
                                        acc[mf][nf][rr * 2 + 1] + __ldg(bias + n + 1));
                *(float2*)&orow[n] = pv;
            }
        }
    }
}

// ---------------------------------------------------------------------------
extern "C" void kernel_launch(void* const* d_in, const int* in_sizes, int n_in,
                              void* d_out, int out_size) {
    const float* x      = (const float*)d_in[0];
    const float* w_qkv  = (const float*)d_in[1];
    const float* b_qkv  = (const float*)d_in[2];
    const float* rel    = (const float*)d_in[3];
    const float* w_out  = (const float*)d_in[4];
    const float* b_out  = (const float*)d_in[5];
    float* out = (float*)d_out;

    qkv_gemm_tc<<<dim3(6, 2048), 256>>>(x, w_qkv, b_qkv);
    attn_kernel<<<32768, 64>>>(rel);
    out_gemm_tc<<<dim3(2, 2048), 256>>>(w_out, b_out, out);
}

// round 5
// speedup vs baseline: 1.7873x; 1.5128x over previous
#include <cuda_runtime.h>
#include <cuda_bf16.h>
#include <cstdint>

// ---------------------------------------------------------------------------
// WMSA, b=4, H=W=256, c=256, WS=8, HEAD_DIM=32.
// R5: operands pre-converted to bf16 hi/lo once (weights, gathered x, attn
// output), GEMM staging is pure copy; ldmatrix reuse across split terms;
// attention inner loops vectorized (float4 broadcast LDS).
// ---------------------------------------------------------------------------

#define QKV_SCALE 0.1767766952966369f   // 32^-0.5

__device__ float g_q[67108864];   // [b,win,head,p,d]
__device__ float g_k[67108864];
__device__ float g_v[67108864];

__device__ __nv_bfloat16 g_x_hi[67108864];   // gathered tokens [t][k]
__device__ __nv_bfloat16 g_x_lo[67108864];
__device__ __nv_bfloat16 g_att_hi[67108864]; // attn out [t][c]
__device__ __nv_bfloat16 g_att_lo[67108864];
__device__ __nv_bfloat16 g_wq_hi[196608], g_wq_lo[196608];
__device__ __nv_bfloat16 g_wo_hi[65536],  g_wo_lo[65536];

// ---------------- helpers ----------------
__device__ __forceinline__ uint32_t smem_u32(const void* p) {
    uint32_t a;
    asm("{ .reg .u64 t; cvta.to.shared.u64 t, %1; cvt.u32.u64 %0, t; }"
        : "=r"(a) : "l"(p));
    return a;
}
__device__ __forceinline__ void ldmx4(uint32_t* r, uint32_t addr) {
    asm volatile("ldmatrix.sync.aligned.m8n8.x4.shared.b16 {%0,%1,%2,%3}, [%4];"
                 : "=r"(r[0]), "=r"(r[1]), "=r"(r[2]), "=r"(r[3]) : "r"(addr));
}
__device__ __forceinline__ void mma_bf16(float* c, const uint32_t* a,
                                         uint32_t b0, uint32_t b1) {
    asm volatile(
        "mma.sync.aligned.m16n8k16.row.col.f32.bf16.bf16.f32 "
        "{%0,%1,%2,%3}, {%4,%5,%6,%7}, {%8,%9}, {%0,%1,%2,%3};"
        : "+f"(c[0]), "+f"(c[1]), "+f"(c[2]), "+f"(c[3])
        : "r"(a[0]), "r"(a[1]), "r"(a[2]), "r"(a[3]), "r"(b0), "r"(b1));
}

// Split 8 consecutive fp32 into bf16 hi (rn) and lo (rn of residue), packed.
__device__ __forceinline__ void split8(const float* src, uint4& h, uint4& l) {
    float4 a = *(const float4*)src;
    float4 b = *(const float4*)(src + 4);
    __nv_bfloat16 h0 = __float2bfloat16(a.x), h1 = __float2bfloat16(a.y);
    __nv_bfloat16 h2 = __float2bfloat16(a.z), h3 = __float2bfloat16(a.w);
    __nv_bfloat16 h4 = __float2bfloat16(b.x), h5 = __float2bfloat16(b.y);
    __nv_bfloat16 h6 = __float2bfloat16(b.z), h7 = __float2bfloat16(b.w);
    h.x = (uint32_t)__bfloat16_as_ushort(h0) | ((uint32_t)__bfloat16_as_ushort(h1) << 16);
    h.y = (uint32_t)__bfloat16_as_ushort(h2) | ((uint32_t)__bfloat16_as_ushort(h3) << 16);
    h.z = (uint32_t)__bfloat16_as_ushort(h4) | ((uint32_t)__bfloat16_as_ushort(h5) << 16);
    h.w = (uint32_t)__bfloat16_as_ushort(h6) | ((uint32_t)__bfloat16_as_ushort(h7) << 16);
    __nv_bfloat16 l0 = __float2bfloat16(a.x - __bfloat162float(h0));
    __nv_bfloat16 l1 = __float2bfloat16(a.y - __bfloat162float(h1));
    __nv_bfloat16 l2 = __float2bfloat16(a.z - __bfloat162float(h2));
    __nv_bfloat16 l3 = __float2bfloat16(a.w - __bfloat162float(h3));
    __nv_bfloat16 l4 = __float2bfloat16(b.x - __bfloat162float(h4));
    __nv_bfloat16 l5 = __float2bfloat16(b.y - __bfloat162float(h5));
    __nv_bfloat16 l6 = __float2bfloat16(b.z - __bfloat162float(h6));
    __nv_bfloat16 l7 = __float2bfloat16(b.w - __bfloat162float(h7));
    l.x = (uint32_t)__bfloat16_as_ushort(l0) | ((uint32_t)__bfloat16_as_ushort(l1) << 16);
    l.y = (uint32_t)__bfloat16_as_ushort(l2) | ((uint32_t)__bfloat16_as_ushort(l3) << 16);
    l.z = (uint32_t)__bfloat16_as_ushort(l4) | ((uint32_t)__bfloat16_as_ushort(l5) << 16);
    l.w = (uint32_t)__bfloat16_as_ushort(l6) | ((uint32_t)__bfloat16_as_ushort(l7) << 16);
}

// ---------------------------------------------------------------------------
// Pre-convert kernels
// ---------------------------------------------------------------------------
__global__ __launch_bounds__(256) void cvt_w_kernel(const float* __restrict__ src,
                                                    __nv_bfloat16* __restrict__ hi,
                                                    __nv_bfloat16* __restrict__ lo) {
    const size_t i8 = ((size_t)blockIdx.x * 256 + threadIdx.x) * 8;
    uint4 h, l;
    split8(src + i8, h, l);
    *(uint4*)(hi + i8) = h;
    *(uint4*)(lo + i8) = l;
}

// Gather (roll + window) token t, convert row to bf16 hi/lo at [t][k].
__global__ __launch_bounds__(256) void cvt_x_kernel(const float* __restrict__ x) {
    const size_t i8 = ((size_t)blockIdx.x * 256 + threadIdx.x) * 8;
    const int t  = (int)(i8 >> 8);
    const int k0 = (int)(i8 & 255);
    const int bi  = t >> 16;
    const int rem = t & 65535;
    const int win = rem >> 6;
    const int p   = rem & 63;
    const int hh  = (((win >> 5) << 3) + (p >> 3) + 4) & 255;
    const int wwp = (((win & 31) << 3) + (p & 7) + 4) & 255;
    const float* src = x + ((((size_t)bi << 8) + hh) * 256 + wwp) * 256 + k0;
    uint4 h, l;
    split8(src, h, l);
    *(uint4*)(g_x_hi + i8) = h;
    *(uint4*)(g_x_lo + i8) = l;
}

// Shared tile: 128 rows x 32 k-chunk, stride 40 bf16 (80B).
#define TSTR 40

// ---------------------------------------------------------------------------
// Kernel 1: QKV projection. 128x128 tile, K=256 in 8 chunks of 32,
// 3 split terms with fragment reuse (12 ldmatrix.x4 per warp per chunk).
// ---------------------------------------------------------------------------
__global__ __launch_bounds__(256, 2)
void qkv_gemm_tc(const float* __restrict__ bias) {
    __shared__ __nv_bfloat16 sAhi[128 * TSTR];
    __shared__ __nv_bfloat16 sAlo[128 * TSTR];
    __shared__ __nv_bfloat16 sBhi[128 * TSTR];
    __shared__ __nv_bfloat16 sBlo[128 * TSTR];

    const int tid = threadIdx.x;
    const int bn = blockIdx.x;   // 0..5
    const int bm = blockIdx.y;   // 0..2047
    const int lane = tid & 31;
    const int wid  = tid >> 5;
    const int warpM = wid & 1;
    const int warpN = wid >> 1;

    const int row  = tid >> 1;
    const int half = tid & 1;
    const __nv_bfloat16* aH = g_x_hi + (size_t)(bm * 128 + row) * 256;
    const __nv_bfloat16* aL = g_x_lo + (size_t)(bm * 128 + row) * 256;
    const __nv_bfloat16* bH = g_wq_hi + (size_t)(bn * 128 + row) * 256;
    const __nv_bfloat16* bL = g_wq_lo + (size_t)(bn * 128 + row) * 256;
    __nv_bfloat16* stA_hi = sAhi + row * TSTR + half * 16;
    __nv_bfloat16* stA_lo = sAlo + row * TSTR + half * 16;
    __nv_bfloat16* stB_hi = sBhi + row * TSTR + half * 16;
    __nv_bfloat16* stB_lo = sBlo + row * TSTR + half * 16;

    const uint32_t uAhi = smem_u32(sAhi), uAlo = smem_u32(sAlo);
    const uint32_t uBhi = smem_u32(sBhi), uBlo = smem_u32(sBlo);
    const uint32_t lane_off = (uint32_t)((lane & 15) * (TSTR * 2) + (lane >> 4) * 16);

    float acc[4][4][4];
#pragma unroll
    for (int a = 0; a < 4; a++)
#pragma unroll
        for (int b = 0; b < 4; b++)
#pragma unroll
            for (int cR = 0; cR < 4; cR++) acc[a][b][cR] = 0.f;

    for (int c = 0; c < 8; c++) {
        const int ko = c * 32 + half * 16;
        *(uint4*)(stA_hi)     = *(const uint4*)(aH + ko);
        *(uint4*)(stA_hi + 8) = *(const uint4*)(aH + ko + 8);
        *(uint4*)(stA_lo)     = *(const uint4*)(aL + ko);
        *(uint4*)(stA_lo + 8) = *(const uint4*)(aL + ko + 8);
        *(uint4*)(stB_hi)     = *(const uint4*)(bH + ko);
        *(uint4*)(stB_hi + 8) = *(const uint4*)(bH + ko + 8);
        *(uint4*)(stB_lo)     = *(const uint4*)(bL + ko);
        *(uint4*)(stB_lo + 8) = *(const uint4*)(bL + ko + 8);
        __syncthreads();

#pragma unroll
        for (int ks = 0; ks < 2; ks++) {
            uint32_t ah[4][4], bh[2][4];
#pragma unroll
            for (int mf = 0; mf < 4; mf++)
                ldmx4(ah[mf], uAhi + (warpM * 64 + mf * 16) * (TSTR * 2) + ks * 32 + lane_off);
#pragma unroll
            for (int np = 0; np < 2; np++)
                ldmx4(bh[np], uBhi + (warpN * 32 + np * 16) * (TSTR * 2) + ks * 32 + lane_off);
#pragma unroll
            for (int mf = 0; mf < 4; mf++)
#pragma unroll
                for (int nf = 0; nf < 4; nf++)
                    mma_bf16(acc[mf][nf], ah[mf], bh[nf >> 1][nf & 1], bh[nf >> 1][(nf & 1) + 2]);
            uint32_t al[4][4];
#pragma unroll
            for (int mf = 0; mf < 4; mf++)
                ldmx4(al[mf], uAlo + (warpM * 64 + mf * 16) * (TSTR * 2) + ks * 32 + lane_off);
#pragma unroll
            for (int mf = 0; mf < 4; mf++)
#pragma unroll
                for (int nf = 0; nf < 4; nf++)
                    mma_bf16(acc[mf][nf], al[mf], bh[nf >> 1][nf & 1], bh[nf >> 1][(nf & 1) + 2]);
            uint32_t bl[2][4];
#pragma unroll
            for (int np = 0; np < 2; np++)
                ldmx4(bl[np], uBlo + (warpN * 32 + np * 16) * (TSTR * 2) + ks * 32 + lane_off);
#pragma unroll
            for (int mf = 0; mf < 4; mf++)
#pragma unroll
                for (int nf = 0; nf < 4; nf++)
                    mma_bf16(acc[mf][nf], ah[mf], bl[nf >> 1][nf & 1], bl[nf >> 1][(nf & 1) + 2]);
        }
        __syncthreads();
    }

    float* dst = (bn < 2) ? g_q : ((bn < 4) ? g_k : g_v);
    const bool isq = (bn < 2);
#pragma unroll
    for (int mf = 0; mf < 4; mf++) {
#pragma unroll
        for (int rr = 0; rr < 2; rr++) {
            const int gt   = bm * 128 + warpM * 64 + mf * 16 + (lane >> 2) + rr * 8;
            const int gbi  = gt >> 16;
            const int grem = gt & 65535;
            const int gwin = grem >> 6;
            const int gp   = grem & 63;
            const size_t rowbase = (size_t)(gbi * 1024 + gwin) * 16384 + gp * 32;
#pragma unroll
            for (int nf = 0; nf < 4; nf++) {
                const int n = bn * 128 + warpN * 32 + nf * 8 + (lane & 3) * 2;
                float v0 = acc[mf][nf][rr * 2 + 0] + __ldg(bias + n);
                float v1 = acc[mf][nf][rr * 2 + 1] + __ldg(bias + n + 1);
                if (isq) { v0 *= QKV_SCALE; v1 *= QKV_SCALE; }
                *(float2*)&dst[rowbase + ((n >> 5) & 7) * 2048 + (n & 31)] =
                    make_float2(v0, v1);
            }
        }
    }
}

// ---------------------------------------------------------------------------
// Kernel 2: attention per (b, win, head). 64 threads = one row each.
// Vectorized inner loops (float4 broadcast LDS); writes bf16 hi/lo output.
// ---------------------------------------------------------------------------
__global__ __launch_bounds__(64) void attn_kernel(const float* __restrict__ rel_pos) {
    const int blk  = blockIdx.x;
    const int head = blk & 7;
    const int bw   = blk >> 3;
    const int win  = bw & 1023;
    const bool lastH = ((win >> 5) == 31);
    const bool lastW = ((win & 31) == 31);
    const int p = threadIdx.x;

    __shared__ float k_s[32][68];   // [d][j], 16B-aligned rows
    __shared__ float v_s[64][36];   // [j][d], 16B-aligned rows
    __shared__ float rel_s[240];

    const size_t base = (size_t)blk * 2048;

#pragma unroll
    for (int d4 = 0; d4 < 32; d4 += 4) {
        float4 kv = *(const float4*)&g_k[base + p * 32 + d4];
        k_s[d4 + 0][p] = kv.x; k_s[d4 + 1][p] = kv.y;
        k_s[d4 + 2][p] = kv.z; k_s[d4 + 3][p] = kv.w;
        float4 vv = *(const float4*)&g_v[base + p * 32 + d4];
        *(float4*)&v_s[p][d4] = vv;
    }
    {
        const float* rp = rel_pos + head * 225;
        for (int i = p; i < 225; i += 64) rel_s[i] = rp[i];
    }

    float qreg[32];
#pragma unroll
    for (int d4 = 0; d4 < 32; d4 += 4) {
        float4 qv = *(const float4*)&g_q[base + p * 32 + d4];
        qreg[d4] = qv.x; qreg[d4 + 1] = qv.y;
        qreg[d4 + 2] = qv.z; qreg[d4 + 3] = qv.w;
    }
    __syncthreads();

    const int pi = p >> 3, pj = p & 7;
    const bool ph4 = (pi < 4), pw4 = (pj < 4);

    // Init scores with rel-pos bias + shift mask, then accumulate q.k.
    float sc[64];
#pragma unroll
    for (int j = 0; j < 64; j++) {
        const int qi = j >> 3, qj = j & 7;
        float s = rel_s[(pi - qi + 7) * 15 + (pj - qj + 7)];
        if ((lastH && (ph4 != (qi < 4))) || (lastW && (pw4 != (qj < 4))))
            s = -1e30f;
        sc[j] = s;
    }
#pragma unroll 4
    for (int d = 0; d < 32; d++) {
        const float qd = qreg[d];
#pragma unroll
        for (int j = 0; j < 64; j += 4) {
            float4 kv = *(const float4*)&k_s[d][j];
            sc[j + 0] += qd * kv.x;
            sc[j + 1] += qd * kv.y;
            sc[j + 2] += qd * kv.z;
            sc[j + 3] += qd * kv.w;
        }
    }

    float mx = -3.0e38f;
#pragma unroll
    for (int j = 0; j < 64; j++) mx = fmaxf(mx, sc[j]);
    float sum = 0.f;
#pragma unroll
    for (int j = 0; j < 64; j++) {
        float e = __expf(sc[j] - mx);
        sc[j] = e;
        sum += e;
    }
    const float inv = 1.f / sum;

    float o[32];
#pragma unroll
    for (int d = 0; d < 32; d++) o[d] = 0.f;
#pragma unroll 8
    for (int j = 0; j < 64; j++) {
        const float a = sc[j] * inv;
#pragma unroll
        for (int d4 = 0; d4 < 32; d4 += 4) {
            float4 vv = *(const float4*)&v_s[j][d4];
            o[d4 + 0] += a * vv.x;
            o[d4 + 1] += a * vv.y;
            o[d4 + 2] += a * vv.z;
            o[d4 + 3] += a * vv.w;
        }
    }

    // Write output as bf16 hi/lo (feeds out_gemm staging directly).
    const size_t op = (size_t)(bw * 64 + p) * 256 + head * 32;
#pragma unroll
    for (int g = 0; g < 4; g++) {
        uint4 h, l;
        split8(o + g * 8, h, l);
        *(uint4*)(g_att_hi + op + g * 8) = h;
        *(uint4*)(g_att_lo + op + g * 8) = l;
    }
}

// ---------------------------------------------------------------------------
// Kernel 3: output projection; epilogue = scrambled (nW,b) reshape + roll.
// ---------------------------------------------------------------------------
__global__ __launch_bounds__(256, 2)
void out_gemm_tc(const float* __restrict__ bias, float* __restrict__ out) {
    __shared__ __nv_bfloat16 sAhi[128 * TSTR];
    __shared__ __nv_bfloat16 sAlo[128 * TSTR];
    __shared__ __nv_bfloat16 sBhi[128 * TSTR];
    __shared__ __nv_bfloat16 sBlo[128 * TSTR];

    const int tid = threadIdx.x;
    const int bn = blockIdx.x;   // 0..1
    const int bm = blockIdx.y;   // 0..2047
    const int lane = tid & 31;
    const int wid  = tid >> 5;
    const int warpM = wid & 1;
    const int warpN = wid >> 1;

    const int row  = tid >> 1;
    const int half = tid & 1;
    const __nv_bfloat16* aH = g_att_hi + (size_t)(bm * 128 + row) * 256;
    const __nv_bfloat16* aL = g_att_lo + (size_t)(bm * 128 + row) * 256;
    const __nv_bfloat16* bH = g_wo_hi + (size_t)(bn * 128 + row) * 256;
    const __nv_bfloat16* bL = g_wo_lo + (size_t)(bn * 128 + row) * 256;
    __nv_bfloat16* stA_hi = sAhi + row * TSTR + half * 16;
    __nv_bfloat16* stA_lo = sAlo + row * TSTR + half * 16;
    __nv_bfloat16* stB_hi = sBhi + row * TSTR + half * 16;
    __nv_bfloat16* stB_lo = sBlo + row * TSTR + half * 16;

    const uint32_t uAhi = smem_u32(sAhi), uAlo = smem_u32(sAlo);
    const uint32_t uBhi = smem_u32(sBhi), uBlo = smem_u32(sBlo);
    const uint32_t lane_off = (uint32_t)((lane & 15) * (TSTR * 2) + (lane >> 4) * 16);

    float acc[4][4][4];
#pragma unroll
    for (int a = 0; a < 4; a++)
#pragma unroll
        for (int b = 0; b < 4; b++)
#pragma unroll
            for (int cR = 0; cR < 4; cR++) acc[a][b][cR] = 0.f;

    for (int c = 0; c < 8; c++) {
        const int ko = c * 32 + half * 16;
        *(uint4*)(stA_hi)     = *(const uint4*)(aH + ko);
        *(uint4*)(stA_hi + 8) = *(const uint4*)(aH + ko + 8);
        *(uint4*)(stA_lo)     = *(const uint4*)(aL + ko);
        *(uint4*)(stA_lo + 8) = *(const uint4*)(aL + ko + 8);
        *(uint4*)(stB_hi)     = *(const uint4*)(bH + ko);
        *(uint4*)(stB_hi + 8) = *(const uint4*)(bH + ko + 8);
        *(uint4*)(stB_lo)     = *(const uint4*)(bL + ko);
        *(uint4*)(stB_lo + 8) = *(const uint4*)(bL + ko + 8);
        __syncthreads();

#pragma unroll
        for (int ks = 0; ks < 2; ks++) {
            uint32_t ah[4][4], bh[2][4];
#pragma unroll
            for (int mf = 0; mf < 4; mf++)
                ldmx4(ah[mf], uAhi + (warpM * 64 + mf * 16) * (TSTR * 2) + ks * 32 + lane_off);
#pragma unroll
            for (int np = 0; np < 2; np++)
                ldmx4(bh[np], uBhi + (warpN * 32 + np * 16) * (TSTR * 2) + ks * 32 + lane_off);
#pragma unroll
            for (int mf = 0; mf < 4; mf++)
#pragma unroll
                for (int nf = 0; nf < 4; nf++)
                    mma_bf16(acc[mf][nf], ah[mf], bh[nf >> 1][nf & 1], bh[nf >> 1][(nf & 1) + 2]);
            uint32_t al[4][4];
#pragma unroll
            for (int mf = 0; mf < 4; mf++)
                ldmx4(al[mf], uAlo + (warpM * 64 + mf * 16) * (TSTR * 2) + ks * 32 + lane_off);
#pragma unroll
            for (int mf = 0; mf < 4; mf++)
#pragma unroll
                for (int nf = 0; nf < 4; nf++)
                    mma_bf16(acc[mf][nf], al[mf], bh[nf >> 1][nf & 1], bh[nf >> 1][(nf & 1) + 2]);
            uint32_t bl[2][4];
#pragma unroll
            for (int np = 0; np < 2; np++)
                ldmx4(bl[np], uBlo + (warpN * 32 + np * 16) * (TSTR * 2) + ks * 32 + lane_off);
#pragma unroll
            for (int mf = 0; mf < 4; mf++)
#pragma unroll
                for (int nf = 0; nf < 4; nf++)
                    mma_bf16(acc[mf][nf], ah[mf], bl[nf >> 1][nf & 1], bl[nf >> 1][(nf & 1) + 2]);
        }
        __syncthreads();
    }

#pragma unroll
    for (int mf = 0; mf < 4; mf++) {
#pragma unroll
        for (int rr = 0; rr < 2; rr++) {
            const int gt   = bm * 128 + warpM * 64 + mf * 16 + (lane >> 2) + rr * 8;
            const int gbi  = gt >> 16;        // b_ (attention batch)
            const int grem = gt & 65535;
            const int gwin = grem >> 6;       // n (true window id)
            const int gp   = grem & 63;
            const int L  = gwin * 4 + gbi;    // reference's scrambled flatten
            const int a  = L >> 10;
            const int r  = (L >> 5) & 31;
            const int s  = L & 31;
            const int hh  = ((r << 3) + (gp >> 3) + 4) & 255;
            const int wwp = ((s << 3) + (gp & 7) + 4) & 255;
            float* orow = out + ((((size_t)a << 8) + hh) * 256 + wwp) * 256;
#pragma unroll
            for (int nf = 0; nf < 4; nf++) {
                const int n = bn * 128 + warpN * 32 + nf * 8 + (lane & 3) * 2;
                *(float2*)&orow[n] =
                    make_float2(acc[mf][nf][rr * 2 + 0] + __ldg(bias + n),
                                acc[mf][nf][rr * 2 + 1] + __ldg(bias + n + 1));
            }
        }
    }
}

// ---------------------------------------------------------------------------
extern "C" void kernel_launch(void* const* d_in, const int* in_sizes, int n_in,
                              void* d_out, int out_size) {
    const float* x      = (const float*)d_in[0];
    const float* w_qkv  = (const float*)d_in[1];
    const float* b_qkv  = (const float*)d_in[2];
    const float* rel    = (const float*)d_in[3];
    const float* w_out  = (const float*)d_in[4];
    const float* b_out  = (const float*)d_in[5];
    float* out = (float*)d_out;

    __nv_bfloat16 *wq_hi, *wq_lo, *wo_hi, *wo_lo;
    cudaGetSymbolAddress((void**)&wq_hi, g_wq_hi);
    cudaGetSymbolAddress((void**)&wq_lo, g_wq_lo);
    cudaGetSymbolAddress((void**)&wo_hi, g_wo_hi);
    cudaGetSymbolAddress((void**)&wo_lo, g_wo_lo);

    cvt_x_kernel<<<32768, 256>>>(x);
    cvt_w_kernel<<<96, 256>>>(w_qkv, wq_hi, wq_lo);
    cvt_w_kernel<<<32, 256>>>(w_out, wo_hi, wo_lo);
    qkv_gemm_tc<<<dim3(6, 2048), 256>>>(b_qkv);
    attn_kernel<<<32768, 64>>>(rel);
    out_gemm_tc<<<dim3(2, 2048), 256>>>(b_out, out);
}

// round 7
// speedup vs baseline: 2.4324x; 1.3610x over previous
#include <cuda_runtime.h>
#include <cuda_bf16.h>
#include <cstdint>

// ---------------------------------------------------------------------------
// WMSA, b=4, H=W=256, c=256, WS=8, HEAD_DIM=32.
// R7: R6 fragment-layout architecture with the attn Q/K/V base-stride fix
// (each block owns 256 uint4 of frags, not 128).
// ---------------------------------------------------------------------------

#define QKV_SCALE 0.1767766952966369f   // 32^-0.5

// Fragment arrays (bf16). frag = 256 bf16 = 128 u32 = 32 uint4.
__device__ __align__(16) __nv_bfloat16 g_xf_hi[67108864], g_xf_lo[67108864]; // x A-frags [tf][kf=16]
__device__ __align__(16) __nv_bfloat16 g_wqf_hi[196608],  g_wqf_lo[196608];  // w_qkv B-frags [nf=48][kf=16]
__device__ __align__(16) __nv_bfloat16 g_wof_hi[65536],   g_wof_lo[65536];   // w_out B-frags [nf=16][kf=16]
__device__ __align__(16) __nv_bfloat16 g_qf_hi[67108864], g_qf_lo[67108864]; // per blk: A-frags [tf=4][kf=2]
__device__ __align__(16) __nv_bfloat16 g_kf_hi[67108864], g_kf_lo[67108864]; // per blk: B-frags [nf=4][kf=2]
__device__ __align__(16) __nv_bfloat16 g_vf_hi[67108864], g_vf_lo[67108864]; // per blk: VT B-frags [nf=2][kf=4]
__device__ __align__(16) __nv_bfloat16 g_af_hi[67108864], g_af_lo[67108864]; // attn-out A-frags [tf][kf=16]

// ---------------- helpers ----------------
__device__ __forceinline__ void mma_bf16(float* c, const uint32_t* a,
                                         uint32_t b0, uint32_t b1) {
    asm volatile(
        "mma.sync.aligned.m16n8k16.row.col.f32.bf16.bf16.f32 "
        "{%0,%1,%2,%3}, {%4,%5,%6,%7}, {%8,%9}, {%0,%1,%2,%3};"
        : "+f"(c[0]), "+f"(c[1]), "+f"(c[2]), "+f"(c[3])
        : "r"(a[0]), "r"(a[1]), "r"(a[2]), "r"(a[3]), "r"(b0), "r"(b1));
}
__device__ __forceinline__ void split2(float a, float b, uint32_t& h, uint32_t& l) {
    __nv_bfloat16 ha = __float2bfloat16(a), hb = __float2bfloat16(b);
    h = (uint32_t)__bfloat16_as_ushort(ha) | ((uint32_t)__bfloat16_as_ushort(hb) << 16);
    __nv_bfloat16 la = __float2bfloat16(a - __bfloat162float(ha));
    __nv_bfloat16 lb = __float2bfloat16(b - __bfloat162float(hb));
    l = (uint32_t)__bfloat16_as_ushort(la) | ((uint32_t)__bfloat16_as_ushort(lb) << 16);
}

// ---------------------------------------------------------------------------
// cvt_x: gathered (roll+window) tokens -> A-frags. One thread = one lane slot.
// ---------------------------------------------------------------------------
__global__ __launch_bounds__(256) void cvt_x(const float* __restrict__ x) {
    const int gid  = blockIdx.x * 256 + threadIdx.x;
    const int lane = gid & 31;
    const int f    = gid >> 5;          // frag id = tf*16 + kf
    const int kf   = f & 15, tf = f >> 4;
    const int r    = lane >> 2;         // 0..7
    const int c0   = kf * 16 + 2 * (lane & 3);
    // gather rows t0, t0+8
    int t = tf * 16 + r;
    const float* row0; const float* row1;
    {
        int bi = t >> 16, rem = t & 65535, win = rem >> 6, p = rem & 63;
        int hh = (((win >> 5) << 3) + (p >> 3) + 4) & 255;
        int ww = (((win & 31) << 3) + (p & 7) + 4) & 255;
        row0 = x + ((((size_t)bi << 8) + hh) * 256 + ww) * 256;
        t += 8;
        bi = t >> 16; rem = t & 65535; win = rem >> 6; p = rem & 63;
        hh = (((win >> 5) << 3) + (p >> 3) + 4) & 255;
        ww = (((win & 31) << 3) + (p & 7) + 4) & 255;
        row1 = x + ((((size_t)bi << 8) + hh) * 256 + ww) * 256;
    }
    float2 v00 = *(const float2*)(row0 + c0);
    float2 v10 = *(const float2*)(row1 + c0);
    float2 v01 = *(const float2*)(row0 + c0 + 8);
    float2 v11 = *(const float2*)(row1 + c0 + 8);
    uint4 h, l;
    split2(v00.x, v00.y, h.x, l.x);
    split2(v10.x, v10.y, h.y, l.y);
    split2(v01.x, v01.y, h.z, l.z);
    split2(v11.x, v11.y, h.w, l.w);
    ((uint4*)g_xf_hi)[(size_t)f * 32 + lane] = h;
    ((uint4*)g_xf_lo)[(size_t)f * 32 + lane] = l;
}

// cvt weights (row-major [n][256]) -> B-frags. Same slot math, no gather.
__global__ __launch_bounds__(256) void cvt_w(const float* __restrict__ w,
                                             __nv_bfloat16* __restrict__ hi,
                                             __nv_bfloat16* __restrict__ lo) {
    const int gid  = blockIdx.x * 256 + threadIdx.x;
    const int lane = gid & 31;
    const int f    = gid >> 5;          // nf*16 + kf
    const int kf   = f & 15, nf = f >> 4;
    const int r    = lane >> 2;
    const int c0   = kf * 16 + 2 * (lane & 3);
    const float* row0 = w + (size_t)(nf * 16 + r) * 256;
    const float* row1 = row0 + 8 * 256;
    float2 v00 = *(const float2*)(row0 + c0);
    float2 v10 = *(const float2*)(row1 + c0);
    float2 v01 = *(const float2*)(row0 + c0 + 8);
    float2 v11 = *(const float2*)(row1 + c0 + 8);
    uint4 h, l;
    split2(v00.x, v00.y, h.x, l.x);
    split2(v10.x, v10.y, h.y, l.y);
    split2(v01.x, v01.y, h.z, l.z);
    split2(v11.x, v11.y, h.w, l.w);
    ((uint4*)hi)[(size_t)f * 32 + lane] = h;
    ((uint4*)lo)[(size_t)f * 32 + lane] = l;
}

// ---------------------------------------------------------------------------
// Kernel 1: QKV GEMM, smem-free. CTA 128x128, warp 64x32. 16 kf x 3 terms.
// Epilogue writes Q/K frag-ready + VT frag-ready (bf16 hi/lo).
// ---------------------------------------------------------------------------
__global__ __launch_bounds__(256, 2)
void qkv_gemm(const float* __restrict__ bias) {
    const int tid = threadIdx.x;
    const int bn = blockIdx.x;   // 0..5
    const int bm = blockIdx.y;   // 0..2047
    const int lane = tid & 31;
    const int wid  = tid >> 5;
    const int warpM = wid & 1;
    const int warpN = wid >> 1;

    const uint4* xh = (const uint4*)g_xf_hi;
    const uint4* xl = (const uint4*)g_xf_lo;
    const uint4* wh = (const uint4*)g_wqf_hi;
    const uint4* wl = (const uint4*)g_wqf_lo;
    const int tfb = bm * 8 + warpM * 4;
    const int nfb = bn * 8 + warpN * 2;

    float acc[4][4][4];
#pragma unroll
    for (int a = 0; a < 4; a++)
#pragma unroll
        for (int b = 0; b < 4; b++)
#pragma unroll
            for (int cR = 0; cR < 4; cR++) acc[a][b][cR] = 0.f;

#pragma unroll 2
    for (int kf = 0; kf < 16; kf++) {
        uint4 Ah[4], Bh[2];
#pragma unroll
        for (int mt = 0; mt < 4; mt++)
            Ah[mt] = xh[(size_t)((tfb + mt) * 16 + kf) * 32 + lane];
#pragma unroll
        for (int nb = 0; nb < 2; nb++)
            Bh[nb] = wh[(size_t)((nfb + nb) * 16 + kf) * 32 + lane];
        uint4 Al[4];
#pragma unroll
        for (int mt = 0; mt < 4; mt++)
            Al[mt] = xl[(size_t)((tfb + mt) * 16 + kf) * 32 + lane];
#pragma unroll
        for (int mt = 0; mt < 4; mt++)
#pragma unroll
            for (int nt = 0; nt < 4; nt++) {
                const uint4& B = Bh[nt >> 1];
                mma_bf16(acc[mt][nt], (const uint32_t*)&Ah[mt],
                         (nt & 1) ? B.y : B.x, (nt & 1) ? B.w : B.z);
            }
#pragma unroll
        for (int mt = 0; mt < 4; mt++)
#pragma unroll
            for (int nt = 0; nt < 4; nt++) {
                const uint4& B = Bh[nt >> 1];
                mma_bf16(acc[mt][nt], (const uint32_t*)&Al[mt],
                         (nt & 1) ? B.y : B.x, (nt & 1) ? B.w : B.z);
            }
        uint4 Bl[2];
#pragma unroll
        for (int nb = 0; nb < 2; nb++)
            Bl[nb] = wl[(size_t)((nfb + nb) * 16 + kf) * 32 + lane];
#pragma unroll
        for (int mt = 0; mt < 4; mt++)
#pragma unroll
            for (int nt = 0; nt < 4; nt++) {
                const uint4& B = Bl[nt >> 1];
                mma_bf16(acc[mt][nt], (const uint32_t*)&Ah[mt],
                         (nt & 1) ? B.y : B.x, (nt & 1) ? B.w : B.z);
            }
    }

    // Epilogue
    const bool isq = (bn < 2);
    const bool isv = (bn >= 4);
    const int bwq = bm * 2 + warpM;            // b*1024+win for this warp
#pragma unroll
    for (int nt = 0; nt < 4; nt++) {
        const int n = bn * 128 + warpN * 32 + nt * 8 + 2 * (lane & 3);
        const float b0 = __ldg(bias + n), b1 = __ldg(bias + n + 1);
        const int head = (n >> 5) & 7;
        const int d0 = n & 31;
        const size_t blkbase = ((size_t)bwq * 8 + head) * 1024;  // u32 units
#pragma unroll
        for (int mt = 0; mt < 4; mt++) {
#pragma unroll
            for (int rr = 0; rr < 2; rr++) {
                float v0 = acc[mt][nt][rr * 2 + 0] + b0;
                float v1 = acc[mt][nt][rr * 2 + 1] + b1;
                if (isq) { v0 *= QKV_SCALE; v1 *= QKV_SCALE; }
                const int gp = mt * 16 + (lane >> 2) + rr * 8;
                if (!isv) {
                    uint32_t h, l;
                    split2(v0, v1, h, l);
                    const int frag = (gp >> 4) * 2 + (d0 >> 4);
                    const int reg = rr + 2 * (nt & 1);
                    const size_t off = blkbase + frag * 128 + lane * 4 + reg;
                    if (isq) {
                        ((uint32_t*)g_qf_hi)[off] = h;
                        ((uint32_t*)g_qf_lo)[off] = l;
                    } else {
                        ((uint32_t*)g_kf_hi)[off] = h;
                        ((uint32_t*)g_kf_lo)[off] = l;
                    }
                } else {
                    // VT B-frags: pair tokens via shfl_xor(4)
                    const float p0 = __shfl_xor_sync(0xffffffffu, v0, 4);
                    const float p1 = __shfl_xor_sync(0xffffffffu, v1, 4);
                    const bool odd = (lane >> 2) & 1;
                    const float e0 = odd ? p1 : v0;
                    const float e1 = odd ? v1 : p0;
                    const int dmy = d0 + (odd ? 1 : 0);
                    const int gpe = gp & ~1;
                    const int frag = (dmy >> 4) * 4 + (gpe >> 4);
                    const int lane2 = (dmy & 7) * 4 + ((gpe & 7) >> 1);
                    const int reg = (nt & 1) + 2 * rr;
                    uint32_t h, l;
                    split2(e0, e1, h, l);
                    const size_t off = blkbase + frag * 128 + lane2 * 4 + reg;
                    ((uint32_t*)g_vf_hi)[off] = h;
                    ((uint32_t*)g_vf_lo)[off] = l;
                }
            }
        }
    }
}

// ---------------------------------------------------------------------------
// Kernel 2: attention via mma. One block (64 thr, 2 warps) per (b,win,head).
// Warp w: query rows 32w..32w+31. S = Q K^T (3-term), softmax, O = P V (3-term).
// ---------------------------------------------------------------------------
__global__ __launch_bounds__(64) void attn_kernel(const float* __restrict__ rel_pos) {
    const int blk  = blockIdx.x;
    const int head = blk & 7;
    const int bw   = blk >> 3;
    const int win  = bw & 1023;
    const bool lastH = ((win >> 5) == 31);
    const bool lastW = ((win & 31) == 31);
    const int lane = threadIdx.x & 31;
    const int warp = threadIdx.x >> 5;

    __shared__ float rel_s[240];
    for (int i = threadIdx.x; i < 225; i += 64) rel_s[i] = rel_pos[head * 225 + i];
    __syncthreads();

    // Each block owns 8 frags x 32 uint4 = 256 uint4 per array. (R7 fix: *256)
    const uint4* qh = (const uint4*)g_qf_hi + (size_t)blk * 256;
    const uint4* ql = (const uint4*)g_qf_lo + (size_t)blk * 256;
    const uint4* kh = (const uint4*)g_kf_hi + (size_t)blk * 256;
    const uint4* kl = (const uint4*)g_kf_lo + (size_t)blk * 256;
    const uint4* vh = (const uint4*)g_vf_hi + (size_t)blk * 256;
    const uint4* vl = (const uint4*)g_vf_lo + (size_t)blk * 256;

    float S[2][8][4];
#pragma unroll
    for (int a = 0; a < 2; a++)
#pragma unroll
        for (int b = 0; b < 8; b++)
#pragma unroll
            for (int cR = 0; cR < 4; cR++) S[a][b][cR] = 0.f;

    {
        uint4 Q[2][2], K[4][2];
#pragma unroll
        for (int mt = 0; mt < 2; mt++)
#pragma unroll
            for (int kf = 0; kf < 2; kf++)
                Q[mt][kf] = qh[((2 * warp + mt) * 2 + kf) * 32 + lane];
#pragma unroll
        for (int nf = 0; nf < 4; nf++)
#pragma unroll
            for (int kf = 0; kf < 2; kf++)
                K[nf][kf] = kh[(nf * 2 + kf) * 32 + lane];
#pragma unroll
        for (int kf = 0; kf < 2; kf++)
#pragma unroll
            for (int mt = 0; mt < 2; mt++)
#pragma unroll
                for (int nt = 0; nt < 8; nt++) {
                    const uint4& B = K[nt >> 1][kf];
                    mma_bf16(S[mt][nt], (const uint32_t*)&Q[mt][kf],
                             (nt & 1) ? B.y : B.x, (nt & 1) ? B.w : B.z);
                }
        uint4 Q2[2][2];
#pragma unroll
        for (int mt = 0; mt < 2; mt++)
#pragma unroll
            for (int kf = 0; kf < 2; kf++)
                Q2[mt][kf] = ql[((2 * warp + mt) * 2 + kf) * 32 + lane];
#pragma unroll
        for (int kf = 0; kf < 2; kf++)
#pragma unroll
            for (int mt = 0; mt < 2; mt++)
#pragma unroll
                for (int nt = 0; nt < 8; nt++) {
                    const uint4& B = K[nt >> 1][kf];
                    mma_bf16(S[mt][nt], (const uint32_t*)&Q2[mt][kf],
                             (nt & 1) ? B.y : B.x, (nt & 1) ? B.w : B.z);
                }
#pragma unroll
        for (int nf = 0; nf < 4; nf++)
#pragma unroll
            for (int kf = 0; kf < 2; kf++)
                K[nf][kf] = kl[(nf * 2 + kf) * 32 + lane];
#pragma unroll
        for (int kf = 0; kf < 2; kf++)
#pragma unroll
            for (int mt = 0; mt < 2; mt++)
#pragma unroll
                for (int nt = 0; nt < 8; nt++) {
                    const uint4& B = K[nt >> 1][kf];
                    mma_bf16(S[mt][nt], (const uint32_t*)&Q[mt][kf],
                             (nt & 1) ? B.y : B.x, (nt & 1) ? B.w : B.z);
                }
    }

    // bias + mask
#pragma unroll
    for (int mt = 0; mt < 2; mt++) {
        const int p_lo = warp * 32 + mt * 16 + (lane >> 2);
        const int p_hi = p_lo + 8;
        const int pi0 = p_lo >> 3, pj0 = p_lo & 7;
        const int pi1 = p_hi >> 3, pj1 = p_hi & 7;
#pragma unroll
        for (int nt = 0; nt < 8; nt++) {
            const int j0 = nt * 8 + 2 * (lane & 3);
#pragma unroll
            for (int jj = 0; jj < 2; jj++) {
                const int j = j0 + jj;
                const int qi = j >> 3, qj = j & 7;
                float r0 = rel_s[(pi0 - qi + 7) * 15 + (pj0 - qj + 7)];
                float r1 = rel_s[(pi1 - qi + 7) * 15 + (pj1 - qj + 7)];
                float s0 = S[mt][nt][jj] + r0;
                float s1 = S[mt][nt][2 + jj] + r1;
                if ((lastH && ((pi0 < 4) != (qi < 4))) || (lastW && ((pj0 < 4) != (qj < 4))))
                    s0 = -1e30f;
                if ((lastH && ((pi1 < 4) != (qi < 4))) || (lastW && ((pj1 < 4) != (qj < 4))))
                    s1 = -1e30f;
                S[mt][nt][jj] = s0;
                S[mt][nt][2 + jj] = s1;
            }
        }
    }

    // softmax per row (regs {0,1} row p_lo, {2,3} row p_hi; cols across lane quad)
    float O[2][4][4];
#pragma unroll
    for (int a = 0; a < 2; a++)
#pragma unroll
        for (int b = 0; b < 4; b++)
#pragma unroll
            for (int cR = 0; cR < 4; cR++) O[a][b][cR] = 0.f;

    uint32_t Ph[2][4][4], Pl[2][4][4];
#pragma unroll
    for (int mt = 0; mt < 2; mt++) {
        float m0 = -3.0e38f, m1 = -3.0e38f;
#pragma unroll
        for (int nt = 0; nt < 8; nt++) {
            m0 = fmaxf(m0, fmaxf(S[mt][nt][0], S[mt][nt][1]));
            m1 = fmaxf(m1, fmaxf(S[mt][nt][2], S[mt][nt][3]));
        }
        m0 = fmaxf(m0, __shfl_xor_sync(0xffffffffu, m0, 1));
        m0 = fmaxf(m0, __shfl_xor_sync(0xffffffffu, m0, 2));
        m1 = fmaxf(m1, __shfl_xor_sync(0xffffffffu, m1, 1));
        m1 = fmaxf(m1, __shfl_xor_sync(0xffffffffu, m1, 2));
        float s0 = 0.f, s1 = 0.f;
#pragma unroll
        for (int nt = 0; nt < 8; nt++) {
            S[mt][nt][0] = __expf(S[mt][nt][0] - m0);
            S[mt][nt][1] = __expf(S[mt][nt][1] - m0);
            S[mt][nt][2] = __expf(S[mt][nt][2] - m1);
            S[mt][nt][3] = __expf(S[mt][nt][3] - m1);
            s0 += S[mt][nt][0] + S[mt][nt][1];
            s1 += S[mt][nt][2] + S[mt][nt][3];
        }
        s0 += __shfl_xor_sync(0xffffffffu, s0, 1);
        s0 += __shfl_xor_sync(0xffffffffu, s0, 2);
        s1 += __shfl_xor_sync(0xffffffffu, s1, 1);
        s1 += __shfl_xor_sync(0xffffffffu, s1, 2);
        const float i0 = 1.f / s0, i1 = 1.f / s1;
        // pack P as A-frags: kf covers nt pair (2kf, 2kf+1)
#pragma unroll
        for (int kf = 0; kf < 4; kf++) {
            split2(S[mt][2 * kf][0] * i0, S[mt][2 * kf][1] * i0, Ph[mt][kf][0], Pl[mt][kf][0]);
            split2(S[mt][2 * kf][2] * i1, S[mt][2 * kf][3] * i1, Ph[mt][kf][1], Pl[mt][kf][1]);
            split2(S[mt][2 * kf + 1][0] * i0, S[mt][2 * kf + 1][1] * i0, Ph[mt][kf][2], Pl[mt][kf][2]);
            split2(S[mt][2 * kf + 1][2] * i1, S[mt][2 * kf + 1][3] * i1, Ph[mt][kf][3], Pl[mt][kf][3]);
        }
    }

    {
        uint4 V[2][4];
#pragma unroll
        for (int nf = 0; nf < 2; nf++)
#pragma unroll
            for (int kf = 0; kf < 4; kf++)
                V[nf][kf] = vh[(nf * 4 + kf) * 32 + lane];
#pragma unroll
        for (int kf = 0; kf < 4; kf++)
#pragma unroll
            for (int mt = 0; mt < 2; mt++)
#pragma unroll
                for (int nd = 0; nd < 4; nd++) {
                    const uint4& B = V[nd >> 1][kf];
                    mma_bf16(O[mt][nd], Ph[mt][kf],
                             (nd & 1) ? B.y : B.x, (nd & 1) ? B.w : B.z);
                }
#pragma unroll
        for (int kf = 0; kf < 4; kf++)
#pragma unroll
            for (int mt = 0; mt < 2; mt++)
#pragma unroll
                for (int nd = 0; nd < 4; nd++) {
                    const uint4& B = V[nd >> 1][kf];
                    mma_bf16(O[mt][nd], Pl[mt][kf],
                             (nd & 1) ? B.y : B.x, (nd & 1) ? B.w : B.z);
                }
#pragma unroll
        for (int nf = 0; nf < 2; nf++)
#pragma unroll
            for (int kf = 0; kf < 4; kf++)
                V[nf][kf] = vl[(nf * 4 + kf) * 32 + lane];
#pragma unroll
        for (int kf = 0; kf < 4; kf++)
#pragma unroll
            for (int mt = 0; mt < 2; mt++)
#pragma unroll
                for (int nd = 0; nd < 4; nd++) {
                    const uint4& B = V[nd >> 1][kf];
                    mma_bf16(O[mt][nd], Ph[mt][kf],
                             (nd & 1) ? B.y : B.x, (nd & 1) ? B.w : B.z);
                }
    }

    // Epilogue: O -> attn-out A-frags (t = bw*64 + p, channel = head*32 + d)
#pragma unroll
    for (int mt = 0; mt < 2; mt++) {
        const int tf = bw * 4 + warp * 2 + mt;
#pragma unroll
        for (int nd = 0; nd < 4; nd++) {
            const int ch = head * 32 + nd * 8 + 2 * (lane & 3);
            const int chf = ch >> 4;
            uint32_t h0, l0, h1, l1;
            split2(O[mt][nd][0], O[mt][nd][1], h0, l0);
            split2(O[mt][nd][2], O[mt][nd][3], h1, l1);
            const size_t off = ((size_t)tf * 16 + chf) * 128 + lane * 4 + 2 * (nd & 1);
            ((uint32_t*)g_af_hi)[off]     = h0;
            ((uint32_t*)g_af_hi)[off + 1] = h1;
            ((uint32_t*)g_af_lo)[off]     = l0;
            ((uint32_t*)g_af_lo)[off + 1] = l1;
        }
    }
}

// ---------------------------------------------------------------------------
// Kernel 3: output projection, smem-free; epilogue = scrambled reshape + roll.
// ---------------------------------------------------------------------------
__global__ __launch_bounds__(256, 2)
void out_gemm(const float* __restrict__ bias, float* __restrict__ out) {
    const int tid = threadIdx.x;
    const int bn = blockIdx.x;   // 0..1
    const int bm = blockIdx.y;   // 0..2047
    const int lane = tid & 31;
    const int wid  = tid >> 5;
    const int warpM = wid & 1;
    const int warpN = wid >> 1;

    const uint4* xh = (const uint4*)g_af_hi;
    const uint4* xl = (const uint4*)g_af_lo;
    const uint4* wh = (const uint4*)g_wof_hi;
    const uint4* wl = (const uint4*)g_wof_lo;
    const int tfb = bm * 8 + warpM * 4;
    const int nfb = bn * 8 + warpN * 2;

    float acc[4][4][4];
#pragma unroll
    for (int a = 0; a < 4; a++)
#pragma unroll
        for (int b = 0; b < 4; b++)
#pragma unroll
            for (int cR = 0; cR < 4; cR++) acc[a][b][cR] = 0.f;

#pragma unroll 2
    for (int kf = 0; kf < 16; kf++) {
        uint4 Ah[4], Bh[2];
#pragma unroll
        for (int mt = 0; mt < 4; mt++)
            Ah[mt] = xh[(size_t)((tfb + mt) * 16 + kf) * 32 + lane];
#pragma unroll
        for (int nb = 0; nb < 2; nb++)
            Bh[nb] = wh[(size_t)((nfb + nb) * 16 + kf) * 32 + lane];
        uint4 Al[4];
#pragma unroll
        for (int mt = 0; mt < 4; mt++)
            Al[mt] = xl[(size_t)((tfb + mt) * 16 + kf) * 32 + lane];
#pragma unroll
        for (int mt = 0; mt < 4; mt++)
#pragma unroll
            for (int nt = 0; nt < 4; nt++) {
                const uint4& B = Bh[nt >> 1];
                mma_bf16(acc[mt][nt], (const uint32_t*)&Ah[mt],
                         (nt & 1) ? B.y : B.x, (nt & 1) ? B.w : B.z);
            }
#pragma unroll
        for (int mt = 0; mt < 4; mt++)
#pragma unroll
            for (int nt = 0; nt < 4; nt++) {
                const uint4& B = Bh[nt >> 1];
                mma_bf16(acc[mt][nt], (const uint32_t*)&Al[mt],
                         (nt & 1) ? B.y : B.x, (nt & 1) ? B.w : B.z);
            }
        uint4 Bl[2];
#pragma unroll
        for (int nb = 0; nb < 2; nb++)
            Bl[nb] = wl[(size_t)((nfb + nb) * 16 + kf) * 32 + lane];
#pragma unroll
        for (int mt = 0; mt < 4; mt++)
#pragma unroll
            for (int nt = 0; nt < 4; nt++) {
                const uint4& B = Bl[nt >> 1];
                mma_bf16(acc[mt][nt], (const uint32_t*)&Ah[mt],
                         (nt & 1) ? B.y : B.x, (nt & 1) ? B.w : B.z);
            }
    }

#pragma unroll
    for (int mt = 0; mt < 4; mt++) {
#pragma unroll
        for (int rr = 0; rr < 2; rr++) {
            const int gt   = bm * 128 + warpM * 64 + mt * 16 + (lane >> 2) + rr * 8;
            const int gbi  = gt >> 16;
            const int grem = gt & 65535;
            const int gwin = grem >> 6;
            const int gp   = grem & 63;
            const int L  = gwin * 4 + gbi;    // reference's scrambled flatten
            const int a  = L >> 10;
            const int r  = (L >> 5) & 31;
            const int s  = L & 31;
            const int hh  = ((r << 3) + (gp >> 3) + 4) & 255;
            const int wwp = ((s << 3) + (gp & 7) + 4) & 255;
            float* orow = out + ((((size_t)a << 8) + hh) * 256 + wwp) * 256;
#pragma unroll
            for (int nt = 0; nt < 4; nt++) {
                const int n = bn * 128 + warpN * 32 + nt * 8 + 2 * (lane & 3);
                *(float2*)&orow[n] =
                    make_float2(acc[mt][nt][rr * 2 + 0] + __ldg(bias + n),
                                acc[mt][nt][rr * 2 + 1] + __ldg(bias + n + 1));
            }
        }
    }
}

// ---------------------------------------------------------------------------
extern "C" void kernel_launch(void* const* d_in, const int* in_sizes, int n_in,
                              void* d_out, int out_size) {
    const float* x      = (const float*)d_in[0];
    const float* w_qkv  = (const float*)d_in[1];
    const float* b_qkv  = (const float*)d_in[2];
    const float* rel    = (const float*)d_in[3];
    const float* w_out  = (const float*)d_in[4];
    const float* b_out  = (const float*)d_in[5];
    float* out = (float*)d_out;

    __nv_bfloat16 *wq_hi, *wq_lo, *wo_hi, *wo_lo;
    cudaGetSymbolAddress((void**)&wq_hi, g_wqf_hi);
    cudaGetSymbolAddress((void**)&wq_lo, g_wqf_lo);
    cudaGetSymbolAddress((void**)&wo_hi, g_wof_hi);
    cudaGetSymbolAddress((void**)&wo_lo, g_wof_lo);

    cvt_x<<<32768, 256>>>(x);
    cvt_w<<<96, 256>>>(w_qkv, wq_hi, wq_lo);
    cvt_w<<<32, 256>>>(w_out, wo_hi, wo_lo);
    qkv_gemm<<<dim3(6, 2048), 256>>>(b_qkv);
    attn_kernel<<<32768, 64>>>(rel);
    out_gemm<<<dim3(2, 2048), 256>>>(b_out, out);
}